// round 9
// baseline (speedup 1.0000x reference)
#include <cuda_runtime.h>

// pre_spikes [8,1,8192] f32, W [8192,8192] f32, thr [8,1,8192] f32,
// const_inp [8,1,8192] f32 -> out [8,1,8192] f32.
#define BB      8
#define MM      8192
#define NN      8192
#define KSPLIT  64
#define K_TILE  (MM / KSPLIT)     // 128
#define TPB     128
#define VEC     4
#define NCOLS   (TPB * VEC)       // 512 columns per block
#define NTILES  (NN / NCOLS)      // 16
#define SROWS   4                 // W rows per pipeline stage
#define NSTAGE  4                 // smem ring slots
#define KSTAGES (K_TILE / SROWS)  // 32
#define STAGE_BYTES (SROWS * NCOLS * 4)   // 8192
#define ROW_BYTES   (NCOLS * 4)           // 2048
#define SPIKE_CAP 0.9f

typedef unsigned long long ull;

// L2-resident accumulator [B][N] = 256 KB. Zero at load; the finishing block
// of each N-tile re-zeroes its slice every call (graph-replay invariant).
__device__ float g_accum[(size_t)BB * NN];
// Per-N-tile arrival counters (reset by the finishing block).
__device__ unsigned int g_count[NTILES];

// Packed f32x2 FMA (Blackwell): d = a*b + c on both 32-bit halves.
__device__ __forceinline__ void fma2(ull& d, ull a, ull b, ull c) {
    asm("fma.rn.f32x2 %0, %1, %2, %3;" : "=l"(d) : "l"(a), "l"(b), "l"(c));
}

// 16B vector reduction into global (sm_90+): one L2 atomic op per 4 floats.
__device__ __forceinline__ void redg_v4f32(float* p, ull lo, ull hi) {
    const float2 a = *reinterpret_cast<const float2*>(&lo);
    const float2 b = *reinterpret_cast<const float2*>(&hi);
    asm volatile("red.global.add.v4.f32 [%0], {%1, %2, %3, %4};"
                 :: "l"(p), "f"(a.x), "f"(a.y), "f"(b.x), "f"(b.y)
                 : "memory");
}

// 16B async copy global->shared (LDGSTS), bypassing the register file.
__device__ __forceinline__ void cp16(unsigned dst, const void* src) {
    asm volatile("cp.async.cg.shared.global [%0], [%1], 16;"
                 :: "r"(dst), "l"(src));
}
#define CP_COMMIT() asm volatile("cp.async.commit_group;" ::: "memory")
#define CP_WAIT(n)  asm volatile("cp.async.wait_group %0;" :: "n"(n) : "memory")

__global__ __launch_bounds__(TPB, 5)
void snn_fused(const float* __restrict__ pre,
               const float* __restrict__ W,
               const float* __restrict__ thr,
               const float* __restrict__ cinp,
               float* __restrict__ out)
{
    // W ring: 4 slots x 4 rows x 512 cols = 32 KB. Each thread cp.asyncs and
    // later consumes ONLY its own 16B per row -> no mainloop __syncthreads.
    __shared__ __align__(16) float wbuf[NSTAGE][SROWS][NCOLS];
    // Pre-spike chunk, amplitude splatted into both halves of an f32x2. 8 KB.
    __shared__ ull sp2[K_TILE][BB];
    __shared__ bool s_last;

    const int ks = blockIdx.y;
    const int k0 = ks * K_TILE;
    const int tile = blockIdx.x;
    const int n0 = tile * NCOLS + threadIdx.x * VEC;

    const float* wsrc = W + (size_t)k0 * NN + n0;     // this thread's column
    const unsigned wdst =
        (unsigned)__cvta_generic_to_shared(&wbuf[0][0][threadIdx.x * VEC]);

    // ---- Pipeline prologue: issue NSTAGE-1 stages BEFORE sp2 staging so the
    // first ~1700B/thread of W loads overlap the spike setup. ----
#pragma unroll
    for (int s = 0; s < NSTAGE - 1; s++) {
#pragma unroll
        for (int r = 0; r < SROWS; r++)
            cp16(wdst + s * STAGE_BYTES + r * ROW_BYTES,
                 wsrc + (size_t)(s * SROWS + r) * NN);
        CP_COMMIT();
    }

    for (int i = threadIdx.x; i < K_TILE * BB; i += TPB) {
        const int b = i >> 7;            // i / K_TILE (K_TILE = 128)
        const int m = i & (K_TILE - 1);
        const float p = pre[(size_t)b * MM + k0 + m];
        ull pk;
        asm("mov.b64 %0, {%1, %1};" : "=l"(pk) : "f"(p));
        sp2[m][b] = pk;
    }
    __syncthreads();

    // 8 batches x 4 columns = 16 f32x2 accumulators.
    ull acc[BB][2];
#pragma unroll
    for (int b = 0; b < BB; b++) { acc[b][0] = 0ULL; acc[b][1] = 0ULL; }

    // Consume one ring slot (SROWS rows) from smem.
    auto consume = [&](int slot, int m0) {
#pragma unroll
        for (int r = 0; r < SROWS; r++) {
            const ulonglong2 w = *reinterpret_cast<const ulonglong2*>(
                &wbuf[slot][r][threadIdx.x * VEC]);
            const ulonglong2* pv =
                reinterpret_cast<const ulonglong2*>(&sp2[m0 + r][0]);
            const ulonglong2 p01 = pv[0];
            const ulonglong2 p23 = pv[1];
            const ulonglong2 p45 = pv[2];
            const ulonglong2 p67 = pv[3];
            fma2(acc[0][0], p01.x, w.x, acc[0][0]); fma2(acc[0][1], p01.x, w.y, acc[0][1]);
            fma2(acc[1][0], p01.y, w.x, acc[1][0]); fma2(acc[1][1], p01.y, w.y, acc[1][1]);
            fma2(acc[2][0], p23.x, w.x, acc[2][0]); fma2(acc[2][1], p23.x, w.y, acc[2][1]);
            fma2(acc[3][0], p23.y, w.x, acc[3][0]); fma2(acc[3][1], p23.y, w.y, acc[3][1]);
            fma2(acc[4][0], p45.x, w.x, acc[4][0]); fma2(acc[4][1], p45.x, w.y, acc[4][1]);
            fma2(acc[5][0], p45.y, w.x, acc[5][0]); fma2(acc[5][1], p45.y, w.y, acc[5][1]);
            fma2(acc[6][0], p67.x, w.x, acc[6][0]); fma2(acc[6][1], p67.x, w.y, acc[6][1]);
            fma2(acc[7][0], p67.y, w.x, acc[7][0]); fma2(acc[7][1], p67.y, w.y, acc[7][1]);
        }
    };

    // ---- Mainloop: wait for stage s, immediately issue stage s+3 into the
    // slot freed two iterations ago, then consume s. Per-thread group
    // tracking only; the LSU stays 3 stages (~48 rows) ahead continuously. ----
#pragma unroll 1
    for (int s = 0; s < KSTAGES - (NSTAGE - 1); s++) {
        CP_WAIT(2);                               // stage s landed
        const int si = s + NSTAGE - 1;
        const unsigned dsti = wdst + (si & (NSTAGE - 1)) * STAGE_BYTES;
#pragma unroll
        for (int r = 0; r < SROWS; r++)
            cp16(dsti + r * ROW_BYTES, wsrc + (size_t)(si * SROWS + r) * NN);
        CP_COMMIT();
        consume(s & (NSTAGE - 1), s * SROWS);
    }
    // Pipeline drain: last 3 stages.
    CP_WAIT(2); consume((KSTAGES - 3) & (NSTAGE - 1), (KSTAGES - 3) * SROWS);
    CP_WAIT(1); consume((KSTAGES - 2) & (NSTAGE - 1), (KSTAGES - 2) * SROWS);
    CP_WAIT(0); consume((KSTAGES - 1) & (NSTAGE - 1), (KSTAGES - 1) * SROWS);

    // Accumulate partials into the L2-resident accumulator.
#pragma unroll
    for (int b = 0; b < BB; b++) {
        redg_v4f32(&g_accum[(size_t)b * NN + n0], acc[b][0], acc[b][1]);
    }

    // ---- Arrival protocol (threadfence-reduction pattern) ----
    __threadfence();            // make this thread's REDs globally visible
    __syncthreads();            // all threads' REDs+fences precede the bump
    if (threadIdx.x == 0) {
        const unsigned int prev = atomicAdd(&g_count[tile], 1u);
        s_last = (prev == KSPLIT - 1);
    }
    __syncthreads();
    if (!s_last) return;

    // ---- Last block of this N-tile: epilogue, 8 batches x 512 columns ----
    __threadfence();            // acquire: see all other blocks' REDs

    const int nb = tile * NCOLS;
    // 4096 elements = 1024 float4; 8 float4 per thread.
#pragma unroll
    for (int v = 0; v < 8; v++) {
        const int e = (v * TPB + threadIdx.x) * VEC;   // 0..4095, vec-aligned
        const int b = e >> 9;                          // e / NCOLS
        const int n = nb + (e & (NCOLS - 1));
        const size_t idx = (size_t)b * NN + n;

        float4 s = *reinterpret_cast<const float4*>(&g_accum[idx]);
        const float4 c = *reinterpret_cast<const float4*>(&cinp[idx]);
        const float4 t = *reinterpret_cast<const float4*>(&thr[idx]);
        s.x = fminf(fmaxf(s.x + c.x - t.x, 0.f), SPIKE_CAP);
        s.y = fminf(fmaxf(s.y + c.y - t.y, 0.f), SPIKE_CAP);
        s.z = fminf(fmaxf(s.z + c.z - t.z, 0.f), SPIKE_CAP);
        s.w = fminf(fmaxf(s.w + c.w - t.w, 0.f), SPIKE_CAP);
        *reinterpret_cast<float4*>(&out[idx]) = s;

        // Restore the zero invariant for the next graph replay.
        *reinterpret_cast<float4*>(&g_accum[idx]) =
            make_float4(0.f, 0.f, 0.f, 0.f);
    }
    if (threadIdx.x == 0) g_count[tile] = 0u;   // reset counter for next call
}

extern "C" void kernel_launch(void* const* d_in, const int* in_sizes, int n_in,
                              void* d_out, int out_size)
{
    const float* pre  = (const float*)d_in[0];  // pre_spikes [8,1,8192]
    const float* W    = (const float*)d_in[1];  // W [8192,8192]
    const float* thr  = (const float*)d_in[2];  // thr [8,1,8192]
    const float* cinp = (const float*)d_in[3];  // const_inp [8,1,8192]
    float* out = (float*)d_out;

    dim3 grid(NTILES, KSPLIT);                  // 16 x 64 = 1024 blocks
    snn_fused<<<grid, TPB>>>(pre, W, thr, cinp, out);
}